// round 13
// baseline (speedup 1.0000x reference)
#include <cuda_runtime.h>
#include <cstdint>

#define N_PTS   4096
#define DIM     128
#define TOPK    4

// ---------------- global scratch ----------------
__device__ float Z_buf[2 * N_PTS * DIM];                 // x @ W  (4 MB)
__device__ unsigned long long Top5x[2 * N_PTS * 16];     // per row: [half][8] exact sorted u64 keys (5 used)

#define BUBBLE5(k)                                            \
    { float _t, _k = (k);                                     \
      _t = fminf(s0, _k); _k = fmaxf(s0, _k); s0 = _t;        \
      _t = fminf(s1, _k); _k = fmaxf(s1, _k); s1 = _t;        \
      _t = fminf(s2, _k); _k = fmaxf(s2, _k); s2 = _t;        \
      _t = fminf(s3, _k); _k = fmaxf(s3, _k); s3 = _t;        \
      s4 = fminf(s4, _k); }

#define SWP(a,b) { unsigned long long _t; if (a > b) { _t = a; a = b; b = _t; } }

#define FMA_F32X2(acc, a, b) \
    asm("fma.rn.f32x2 %0, %1, %2, %3;" : "=l"(acc) : "l"(a), "l"(b), "l"(acc))

// ---------------- kernel 1: per-(32-row, 2048-cand-half) top-5 scan ----------------
// Shifted-space scoring: candidates stored as m=(-2x,-2y,-2z,|q|^2);
// d2' = P·m.xyz + m.w = d2 - |P|^2  (3 FFMA, order-preserving per row).

#define SB_THREADS 512
#define SB_WARPS   16
#define HALF_C     (N_PTS / 2)              // 2048
#define SB_SLICE   (HALF_C / SB_WARPS)      // 128
#define SB_L1      32

#define TREEMERGE()                                                        \
    _Pragma("unroll")                                                      \
    for (int step = 8; step >= 1; step >>= 1) {                            \
        if (warp >= step && warp < 2 * step) {                             \
            float* m = m_s + ((warp - step) * 32 + lane) * 5;              \
            m[0] = s0; m[1] = s1; m[2] = s2; m[3] = s3; m[4] = s4;         \
        }                                                                  \
        __syncthreads();                                                   \
        if (warp < step) {                                                 \
            const float* m = m_s + (warp * 32 + lane) * 5;                 \
            BUBBLE5(m[0]); BUBBLE5(m[1]); BUBBLE5(m[2]);                   \
            BUBBLE5(m[3]); BUBBLE5(m[4]);                                  \
        }                                                                  \
        __syncthreads();                                                   \
    }

__global__ void __launch_bounds__(SB_THREADS, 3)
scan_topk(const float* __restrict__ pos)
{
    extern __shared__ float smemB[];
    float4* pos_s  = (float4*)smemB;                   // [2048] (-2x,-2y,-2z,|q|^2)
    float*  m_s    = (float*)(pos_s + HALF_C);         // [8*32*5]
    float*  base_s = m_s + 8 * 32 * 5;                 // [32*5]
    float*  tau_s  = base_s + 32 * 5;                  // [32]

    const int tid  = threadIdx.x;
    const int warp = tid >> 5;
    const int lane = tid & 31;
    const int rg   = blockIdx.x >> 1;
    const int half = blockIdx.x & 1;
    const int r0   = rg * 32;
    const int b    = r0 >> 12;
    const int n0   = r0 & (N_PTS - 1);
    const int cb   = half * HALF_C;

    // ---- load this half's candidates in shifted form ----
    const float* pb = pos + ((size_t)b * N_PTS + cb) * 3;
    const float4* pb4 = (const float4*)pb;
    for (int g = tid; g < HALF_C / 4; g += SB_THREADS) {
        float4 a = pb4[3*g + 0];
        float4 c = pb4[3*g + 1];
        float4 d = pb4[3*g + 2];
        float px, py, pz; float4 q;
        px = a.x; py = a.y; pz = a.z;
        q.x = -2.f*px; q.y = -2.f*py; q.z = -2.f*pz;
        q.w = fmaf(pz, pz, fmaf(py, py, px * px));
        pos_s[4*g + 0] = q;
        px = a.w; py = c.x; pz = c.y;
        q.x = -2.f*px; q.y = -2.f*py; q.z = -2.f*pz;
        q.w = fmaf(pz, pz, fmaf(py, py, px * px));
        pos_s[4*g + 1] = q;
        px = c.z; py = c.w; pz = d.x;
        q.x = -2.f*px; q.y = -2.f*py; q.z = -2.f*pz;
        q.w = fmaf(pz, pz, fmaf(py, py, px * px));
        pos_s[4*g + 2] = q;
        px = d.y; py = d.z; pz = d.w;
        q.x = -2.f*px; q.y = -2.f*py; q.z = -2.f*pz;
        q.w = fmaf(pz, pz, fmaf(py, py, px * px));
        pos_s[4*g + 3] = q;
    }
    __syncthreads();

    // ---- this lane's row position (raw coords from global) ----
    const float* pr = pos + ((size_t)b * N_PTS + n0 + lane) * 3;
    float Px = __ldg(pr), Py = __ldg(pr + 1), Pz = __ldg(pr + 2);

    const float INF = __int_as_float(0x7f800000);
    float s0 = INF, s1 = INF, s2 = INF, s3 = INF, s4 = INF;

    const int base = warp * SB_SLICE;

    // ---- phase 1: unconditional (32 cands/warp -> 512 samples/half) ----
    #pragma unroll 8
    for (int jj = 0; jj < SB_L1; jj++) {
        const int j = base + jj;
        float4 q = pos_s[j];
        float d2c = fmaf(Px, q.x, fmaf(Py, q.y, fmaf(Pz, q.z, q.w)));
        float k   = __int_as_float((__float_as_int(d2c) & 0xFFFFF000) | (cb + j));
        BUBBLE5(k);
    }

    TREEMERGE();

    if (warp == 0) {
        float* bs = base_s + lane * 5;
        bs[0] = s0; bs[1] = s1; bs[2] = s2; bs[3] = s3; bs[4] = s4;
        // sign-aware round-up past the 12 packed index bits
        unsigned ub = __float_as_uint(s4);
        unsigned ut = ub & 0xFFFFF000u;
        ut = (ub & 0x80000000u) ? (ut - 0x1000u) : (ut + 0x1000u);
        tau_s[lane] = __uint_as_float(ut);
    }
    __syncthreads();

    const float tau = tau_s[lane];

    // ---- phase 2: filtered ----
    s0 = INF; s1 = INF; s2 = INF; s3 = INF; s4 = INF;
    #pragma unroll 8
    for (int jj = SB_L1; jj < SB_SLICE; jj++) {
        const int j = base + jj;
        float4 q = pos_s[j];
        float d2c = fmaf(Px, q.x, fmaf(Py, q.y, fmaf(Pz, q.z, q.w)));
        if (d2c < tau) {
            float k = __int_as_float((__float_as_int(d2c) & 0xFFFFF000) | (cb + j));
            BUBBLE5(k);
        }
    }

    TREEMERGE();

    if (warp == 0) {
        const float* bs = base_s + lane * 5;
        BUBBLE5(bs[0]); BUBBLE5(bs[1]); BUBBLE5(bs[2]);
        BUBBLE5(bs[3]); BUBBLE5(bs[4]);

        // exact difference-form rerank of the 5 survivors
        float cand[5] = { s0, s1, s2, s3, s4 };
        unsigned long long k[5];
        #pragma unroll
        for (int i = 0; i < 5; i++) {
            int jg = __float_as_int(cand[i]) & 0xFFF;   // within-batch index
            float4 m = pos_s[jg - cb];
            float qx = -0.5f * m.x, qy = -0.5f * m.y, qz = -0.5f * m.z;
            float dx = Px - qx, dy = Py - qy, dz = Pz - qz;
            float d2 = fmaf(dz, dz, fmaf(dy, dy, dx * dx));
            k[i] = ((unsigned long long)__float_as_uint(d2) << 32) | (unsigned)jg;
        }
        SWP(k[0],k[1]) SWP(k[3],k[4]) SWP(k[2],k[4]) SWP(k[2],k[3]) SWP(k[0],k[3])
        SWP(k[0],k[2]) SWP(k[1],k[4]) SWP(k[1],k[3]) SWP(k[1],k[2])

        unsigned long long* dst = Top5x + ((size_t)(r0 + lane) * 2 + half) * 8;
        dst[0] = k[0]; dst[1] = k[1]; dst[2] = k[2];
        dst[3] = k[3]; dst[4] = k[4];
    }
}

// ---------------- kernel 2: Z = x @ W via packed f32x2 FMA ----------------
// Block: 64 rows x 64 cols (colh). Accum halves = even-d / odd-d sums.
// w2_s[t][cl] = (W[2t][c], W[2t+1][c]); lane reads its 2 adjacent cols as LDS.128.

#define GA_THREADS 512

__global__ void __launch_bounds__(GA_THREADS, 2)
gemm_xw(const float* __restrict__ x, const float* __restrict__ W)
{
    extern __shared__ float smemA[];
    float2* w2_s = (float2*)smemA;                     // [64][64] float2 = 32 KB
    float*  x_s  = (float*)(w2_s + 64 * 64);           // [64][128] = 32 KB

    const int tid  = threadIdx.x;
    const int warp = tid >> 5;
    const int lane = tid & 31;
    const int gid  = blockIdx.x;                       // 0..255
    const int rg   = gid >> 1;
    const int colh = gid & 1;
    const int g0   = rg * 64;

    // build W pairs: i = t*64 + cl  (coalesced over cl)
    #pragma unroll
    for (int i = tid; i < 64 * 64; i += GA_THREADS) {
        int t = i >> 6, cl = i & 63;
        int c = colh * 64 + cl;
        float we = __ldg(&W[(2*t)     * DIM + c]);
        float wo = __ldg(&W[(2*t + 1) * DIM + c]);
        w2_s[t * 64 + cl] = make_float2(we, wo);
    }
    // x rows
    const float4* xg = (const float4*)x + (size_t)g0 * 32;
    float4* xs4 = (float4*)x_s;
    #pragma unroll
    for (int i = tid; i < 64 * 32; i += GA_THREADS) xs4[i] = xg[i];
    __syncthreads();

    const int r0l = warp * 4;                          // 4 rows per warp
    const unsigned long long* xr0 = (const unsigned long long*)(x_s + (r0l + 0) * DIM);
    const unsigned long long* xr1 = (const unsigned long long*)(x_s + (r0l + 1) * DIM);
    const unsigned long long* xr2 = (const unsigned long long*)(x_s + (r0l + 2) * DIM);
    const unsigned long long* xr3 = (const unsigned long long*)(x_s + (r0l + 3) * DIM);
    const ulonglong2* wv2 = (const ulonglong2*)w2_s;   // [64][32] pairs of u64

    unsigned long long a00 = 0, a01 = 0, a10 = 0, a11 = 0;
    unsigned long long a20 = 0, a21 = 0, a30 = 0, a31 = 0;

    #pragma unroll 8
    for (int t = 0; t < 64; t++) {
        ulonglong2 wp = wv2[t * 32 + lane];            // cols (2lane, 2lane+1), LDS.128
        unsigned long long y0 = xr0[t];                // (x[r][2t], x[r][2t+1]), LDS.64
        unsigned long long y1 = xr1[t];
        unsigned long long y2 = xr2[t];
        unsigned long long y3 = xr3[t];
        FMA_F32X2(a00, y0, wp.x); FMA_F32X2(a01, y0, wp.y);
        FMA_F32X2(a10, y1, wp.x); FMA_F32X2(a11, y1, wp.y);
        FMA_F32X2(a20, y2, wp.x); FMA_F32X2(a21, y2, wp.y);
        FMA_F32X2(a30, y3, wp.x); FMA_F32X2(a31, y3, wp.y);
    }

    // fold even/odd halves, store float2 per row
    const int cg = colh * 64 + 2 * lane;               // global col of pair
    float2* Z2 = (float2*)Z_buf;
    {
        float2 e, o, r;
        #define STORE_ROW(ar0, ar1, rr)                                        \
        {                                                                      \
            e = *(float2*)&ar0; o = *(float2*)&ar1;                            \
            r.x = e.x + e.y;  /* even+odd sums, col 2lane   */                 \
            r.y = o.x + o.y;  /* col 2lane+1 */                                \
            Z2[((size_t)(g0 + r0l + rr) * DIM + cg) >> 1] = r;                 \
        }
        STORE_ROW(a00, a01, 0)
        STORE_ROW(a10, a11, 1)
        STORE_ROW(a20, a21, 2)
        STORE_ROW(a30, a31, 3)
        #undef STORE_ROW
    }
}

// ---------------- kernel 3: merge sorted halves, weights, gather (measured 6.5us) ----------------
#define GC_THREADS 256
#define GC_WARPS   8           // one row per warp

__global__ void __launch_bounds__(GC_THREADS, 8)
finish_gather(const float* __restrict__ bias,
              float* __restrict__ out)
{
    const int tid  = threadIdx.x;
    const int warp = tid >> 5;
    const int lane = tid & 31;
    const int row  = blockIdx.x * GC_WARPS + warp;     // global row (b*4096+n)
    const int b    = row >> 12;

    const unsigned long long* t = Top5x + (size_t)row * 16;
    unsigned long long A0 = __ldg(&t[0]),  A1 = __ldg(&t[1]),
                       A2 = __ldg(&t[2]),  A3 = __ldg(&t[3]);
    unsigned long long B0 = __ldg(&t[8]),  B1 = __ldg(&t[9]),
                       B2 = __ldg(&t[10]), B3 = __ldg(&t[11]);

    float w0,w1,w2,w3; int i0,i1,i2,i3;
    #pragma unroll
    for (int r = 0; r < TOPK; r++) {
        bool ta = A0 < B0;
        unsigned long long v = ta ? A0 : B0;
        if (ta) { A0 = A1; A1 = A2; A2 = A3; A3 = ~0ull; }
        else    { B0 = B1; B1 = B2; B2 = B3; B3 = ~0ull; }
        float d2 = __uint_as_float((unsigned)(v >> 32));
        float ww = expf(-0.5f * (d2 + 1e-8f));
        int   jj = (int)(v & 0xFFFFFFFFull);
        if      (r == 0) { w0 = ww; i0 = jj; }
        else if (r == 1) { w1 = ww; i1 = jj; }
        else if (r == 2) { w2 = ww; i2 = jj; }
        else             { w3 = ww; i3 = jj; }
    }
    float inv = 1.0f / (((w0 + w1) + w2) + w3 + 1e-8f);
    w0 *= inv; w1 *= inv; w2 *= inv; w3 *= inv;

    const float4* Z4 = (const float4*)Z_buf + (size_t)b * N_PTS * 32;
    float4 acc = __ldg(&((const float4*)bias)[lane]);
    float4 z0 = Z4[(size_t)i0 * 32 + lane];
    float4 z1 = Z4[(size_t)i1 * 32 + lane];
    float4 z2 = Z4[(size_t)i2 * 32 + lane];
    float4 z3 = Z4[(size_t)i3 * 32 + lane];
    acc.x = fmaf(w0,z0.x, fmaf(w1,z1.x, fmaf(w2,z2.x, fmaf(w3,z3.x, acc.x))));
    acc.y = fmaf(w0,z0.y, fmaf(w1,z1.y, fmaf(w2,z2.y, fmaf(w3,z3.y, acc.y))));
    acc.z = fmaf(w0,z0.z, fmaf(w1,z1.z, fmaf(w2,z2.z, fmaf(w3,z3.z, acc.z))));
    acc.w = fmaf(w0,z0.w, fmaf(w1,z1.w, fmaf(w2,z2.w, fmaf(w3,z3.w, acc.w))));
    ((float4*)out)[(size_t)row * 32 + lane] = acc;
}

extern "C" void kernel_launch(void* const* d_in, const int* in_sizes, int n_in,
                              void* d_out, int out_size)
{
    const float* x    = (const float*)d_in[0];
    const float* pos  = (const float*)d_in[1];
    const float* W    = (const float*)d_in[2];
    const float* bias = (const float*)d_in[3];
    float* out        = (float*)d_out;

    const int rows = in_sizes[1] / 3;                  // B * N = 8192

    // K1: top-5 scan (512 blocks)
    const size_t smemB = (size_t)HALF_C * 16 + 8*32*5*4 + 32*5*4 + 32*4;   // 38656
    cudaFuncSetAttribute(scan_topk, cudaFuncAttributeMaxDynamicSharedMemorySize, (int)smemB);
    scan_topk<<<(rows / 32) * 2, SB_THREADS, smemB>>>(pos);

    // K2: Z = x @ W (256 blocks, f32x2)
    const size_t smemA = (size_t)64 * 64 * 8 + (size_t)64 * DIM * 4;       // 65536
    cudaFuncSetAttribute(gemm_xw, cudaFuncAttributeMaxDynamicSharedMemorySize, (int)smemA);
    gemm_xw<<<(rows / 64) * 2, GA_THREADS, smemA>>>(x, W);

    // K3: merge + weights + gather
    finish_gather<<<rows / GC_WARPS, GC_THREADS>>>(bias, out);
}